// round 1
// baseline (speedup 1.0000x reference)
#include <cuda_runtime.h>
#include <math.h>

// Problem constants (fixed by setup_inputs)
#define B_ 16
#define T_ 2000
#define U_ 400
#define D_ 512
#define C_ 4096
#define M_ (B_ * T_)   // 32000 rows

// ---------------- device scratch (no allocations allowed) ----------------
__device__ float g_logits[(size_t)M_ * C_];      // 512 MB
__device__ float g_lse[M_];
__device__ float g_lp[(size_t)2 * B_ * T_ * U_]; // 102 MB: [chain][t][u]
__device__ float g_loss[2 * B_];

// logaddexp: max + log(1 + exp(-(|a-b|)))
__device__ __forceinline__ float laef(float a, float b) {
    float mx = fmaxf(a, b);
    float d  = fminf(a, b) - mx;      // <= 0, finite
    return mx + __logf(1.0f + __expf(d));
}

// ---------------- 1) GEMM: logits = x @ W + bias ----------------
// x: (M_, D_) row-major, W: (D_, C_) row-major, out: (M_, C_) row-major
__global__ __launch_bounds__(256) void gemm_kernel(
    const float* __restrict__ A, const float* __restrict__ Wm,
    const float* __restrict__ bias)
{
    const int BK = 16;
    __shared__ float As[16][128];   // [k][m] (transposed)
    __shared__ float Bs[16][128];   // [k][n]

    int bm = blockIdx.y, bn = blockIdx.x;
    int tid = threadIdx.x;                 // 0..255
    int tx = (tid & 15) * 8;               // n offset in tile
    int ty = (tid >> 4) * 8;               // m offset in tile

    float acc[8][8];
#pragma unroll
    for (int i = 0; i < 8; i++)
#pragma unroll
        for (int j = 0; j < 8; j++) acc[i][j] = 0.0f;

    const float* Ab = A + (size_t)bm * 128 * D_;
    const float* Wb = Wm + bn * 128;

    for (int k0 = 0; k0 < D_; k0 += BK) {
        // Load A tile: 128 rows x 16 k = 512 float4
#pragma unroll
        for (int l = 0; l < 2; l++) {
            int idx = tid + l * 256;
            int row = idx >> 2;
            int k4  = (idx & 3) * 4;
            float4 v = *(const float4*)(Ab + (size_t)row * D_ + k0 + k4);
            As[k4 + 0][row] = v.x;
            As[k4 + 1][row] = v.y;
            As[k4 + 2][row] = v.z;
            As[k4 + 3][row] = v.w;
        }
        // Load B tile: 16 k x 128 n = 512 float4 (coalesced)
#pragma unroll
        for (int l = 0; l < 2; l++) {
            int idx = tid + l * 256;
            int row = idx >> 5;
            int c4  = (idx & 31) * 4;
            *(float4*)(&Bs[row][c4]) =
                *(const float4*)(Wb + (size_t)(k0 + row) * C_ + c4);
        }
        __syncthreads();
#pragma unroll
        for (int kk = 0; kk < BK; kk++) {
            float a[8], b[8];
#pragma unroll
            for (int i = 0; i < 8; i++) a[i] = As[kk][ty + i];
#pragma unroll
            for (int j = 0; j < 8; j++) b[j] = Bs[kk][tx + j];
#pragma unroll
            for (int i = 0; i < 8; i++)
#pragma unroll
                for (int j = 0; j < 8; j++)
                    acc[i][j] = fmaf(a[i], b[j], acc[i][j]);
        }
        __syncthreads();
    }

    // epilogue: add bias, store
    float bb[8];
#pragma unroll
    for (int j = 0; j < 8; j++) bb[j] = bias[bn * 128 + tx + j];

#pragma unroll
    for (int i = 0; i < 8; i++) {
        float* Crow = g_logits + (size_t)(bm * 128 + ty + i) * C_ + bn * 128 + tx;
#pragma unroll
        for (int j = 0; j < 8; j += 4) {
            float4 v;
            v.x = acc[i][j + 0] + bb[j + 0];
            v.y = acc[i][j + 1] + bb[j + 1];
            v.z = acc[i][j + 2] + bb[j + 2];
            v.w = acc[i][j + 3] + bb[j + 3];
            *(float4*)(Crow + j) = v;
        }
    }
}

// ---------------- 2) per-row logsumexp over C_ ----------------
__global__ __launch_bounds__(256) void lse_kernel()
{
    int r = blockIdx.x;
    const float4* row = (const float4*)(g_logits + (size_t)r * C_);
    int tid = threadIdx.x;

    float4 v[4];
#pragma unroll
    for (int i = 0; i < 4; i++) v[i] = row[tid + 256 * i];

    float mx = -1e30f;
#pragma unroll
    for (int i = 0; i < 4; i++) {
        mx = fmaxf(mx, fmaxf(fmaxf(v[i].x, v[i].y), fmaxf(v[i].z, v[i].w)));
    }

    __shared__ float red[256];
    red[tid] = mx;
    __syncthreads();
    for (int s = 128; s > 0; s >>= 1) {
        if (tid < s) red[tid] = fmaxf(red[tid], red[tid + s]);
        __syncthreads();
    }
    mx = red[0];
    __syncthreads();

    float sum = 0.0f;
#pragma unroll
    for (int i = 0; i < 4; i++) {
        sum += __expf(v[i].x - mx) + __expf(v[i].y - mx) +
               __expf(v[i].z - mx) + __expf(v[i].w - mx);
    }
    red[tid] = sum;
    __syncthreads();
    for (int s = 128; s > 0; s >>= 1) {
        if (tid < s) red[tid] += red[tid + s];
        __syncthreads();
    }
    if (tid == 0) g_lse[r] = mx + __logf(red[0]);
}

// ---------------- 3) gather lp[chain][t][u] = logit[row, tgt] - lse[row] ----
#define GT 8   // frames per block
__global__ __launch_bounds__(128) void gather_kernel(
    const int* __restrict__ tgt1, const int* __restrict__ tgt2,
    const int* __restrict__ act_lens,
    const int* __restrict__ tl1, const int* __restrict__ tl2)
{
    int chain = blockIdx.y;          // 0..31
    int s = chain >> 4, b = chain & 15;
    const int* tgt = (s ? tgt2 : tgt1) + b * U_;
    int tlen = (s ? tl2 : tl1)[b];
    int alen = act_lens[b];

    int t0 = blockIdx.x * GT;
    if (t0 >= alen) return;
    int te = min(t0 + GT, alen);

    int tid = threadIdx.x;
    int c[4];
    int nu = 0;
    for (int u = tid; u < tlen; u += 128) c[nu++] = tgt[u];

    float* lpc = g_lp + (size_t)chain * T_ * U_;
    for (int t = t0; t < te; t++) {
        const float* lrow = g_logits + (size_t)(b * T_ + t) * C_;
        float lse = g_lse[b * T_ + t];
        float* lprow = lpc + (size_t)t * U_;
        int u = tid;
        for (int i = 0; i < nu; i++, u += 128)
            lprow[u] = __ldg(lrow + c[i]) - lse;
    }
}

// ---------------- 4) alpha recursion per chain ----------------
// alpha[t,u] = logaddexp(alpha[t-1,u], alpha[t-1,u-1]) + lp[t,u], t<alen
__global__ __launch_bounds__(128) void alpha_kernel(
    const int* __restrict__ act_lens,
    const int* __restrict__ tl1, const int* __restrict__ tl2)
{
    int chain = blockIdx.x;
    int s = chain >> 4, b = chain & 15;
    int tlen = (s ? tl2 : tl1)[b];
    int alen = act_lens[b];

    int tid = threadIdx.x, warp = tid >> 5, lane = tid & 31;
    const float* lp = g_lp + (size_t)chain * T_ * U_;
    int u0 = tid * 4;
    bool active = (u0 < tlen);
    const float NEGF = -1e30f;

    __shared__ float bnd[2][4];

    // init from lp[0]
    float4 f0 = active ? *(const float4*)(lp + u0)
                       : make_float4(NEGF, NEGF, NEGF, NEGF);
    float a0, a1, a2, a3;
    if (tid == 0) {
        a0 = f0.x;        a1 = f0.y + NEGF;
        a2 = f0.z + NEGF; a3 = f0.w + NEGF;
    } else {
        a0 = f0.x + NEGF; a1 = f0.y + NEGF;
        a2 = f0.z + NEGF; a3 = f0.w + NEGF;
    }

    // depth-4 prefetch pipeline
    float4 buf[4];
#pragma unroll
    for (int d = 0; d < 4; d++) {
        int t = 1 + d;
        buf[d] = (active && t < alen) ? *(const float4*)(lp + (size_t)t * U_ + u0)
                                      : make_float4(0, 0, 0, 0);
    }

    for (int t = 1; t < alen; t++) {
        float4 cur = buf[(t - 1) & 3];
        int tp = t + 4;
        if (active && tp < alen)
            buf[(t - 1) & 3] = *(const float4*)(lp + (size_t)tp * U_ + u0);

        // boundary: previous-step alpha[u0-1] from left neighbor
        float up = __shfl_up_sync(0xffffffffu, a3, 1);
        int pb = t & 1;
        if (lane == 31) bnd[pb][warp] = a3;
        __syncthreads();
        if (lane == 0) up = (warp == 0) ? NEGF : bnd[pb][warp - 1];

        float n0 = laef(a0, up) + cur.x;
        float n1 = laef(a1, a0) + cur.y;
        float n2 = laef(a2, a1) + cur.z;
        float n3 = laef(a3, a2) + cur.w;
        a0 = n0; a1 = n1; a2 = n2; a3 = n3;
    }

    int ustar = tlen - 1;
    if (tid == (ustar >> 2)) {
        int j = ustar & 3;
        float v = (j == 0) ? a0 : (j == 1) ? a1 : (j == 2) ? a2 : a3;
        g_loss[chain] = -v;
    }
}

// ---------------- 5) final reduction ----------------
__global__ void loss_kernel(float* out)
{
    if (threadIdx.x == 0) {
        float l1 = 0.0f, l2 = 0.0f;
        for (int i = 0; i < 16; i++) { l1 += g_loss[i]; l2 += g_loss[16 + i]; }
        l1 *= (1.0f / 16.0f);
        l2 *= (1.0f / 16.0f);
        out[0] = l1 - 0.5f * l2;
        out[1] = l1;
        out[2] = l2;
    }
}

// ---------------- launch ----------------
extern "C" void kernel_launch(void* const* d_in, const int* in_sizes, int n_in,
                              void* d_out, int out_size)
{
    const float* x    = (const float*)d_in[0];
    const float* W    = (const float*)d_in[1];
    const float* bias = (const float*)d_in[2];
    const int* tgt1   = (const int*)d_in[3];
    const int* tgt2   = (const int*)d_in[4];
    const int* alen   = (const int*)d_in[5];
    const int* tl1    = (const int*)d_in[6];
    const int* tl2    = (const int*)d_in[7];
    float* out = (float*)d_out;

    dim3 ggrid(C_ / 128, M_ / 128);      // (32, 250)
    gemm_kernel<<<ggrid, 256>>>(x, W, bias);

    lse_kernel<<<M_, 256>>>();

    dim3 grid_g((T_ + GT - 1) / GT, 2 * B_);   // (250, 32)
    gather_kernel<<<grid_g, 128>>>(tgt1, tgt2, alen, tl1, tl2);

    alpha_kernel<<<2 * B_, 128>>>(alen, tl1, tl2);

    loss_kernel<<<1, 32>>>(out);
}

// round 2
// speedup vs baseline: 2.9575x; 2.9575x over previous
#include <cuda_runtime.h>
#include <cuda_bf16.h>
#include <math.h>
#include <stdint.h>

#define B_ 16
#define T_ 2000
#define U_ 400
#define D_ 512
#define C_ 4096
#define M_ (B_ * T_)   // 32000
#define NEGF (-1e30f)

// ---------------- device scratch ----------------
__device__ float g_logits[(size_t)M_ * C_];      // 512 MB
__device__ float g_lse[M_];
__device__ float g_lp[(size_t)2 * B_ * T_ * U_]; // 102 MB
__device__ float g_loss[2 * B_];
__device__ __align__(16) __nv_bfloat16 g_xb[(size_t)M_ * D_];
__device__ __align__(16) __nv_bfloat16 g_Wb[(size_t)D_ * C_];

__device__ __forceinline__ float laef(float a, float b) {
    float mx = fmaxf(a, b);
    float d  = fminf(a, b) - mx;
    return mx + __logf(1.0f + __expf(d));
}

// ---------------- 0) fp32 -> bf16 conversion ----------------
__device__ __forceinline__ void cvt8(const float* __restrict__ in,
                                     __nv_bfloat16* __restrict__ out, int i) {
    const float4* p = (const float4*)in + (size_t)i * 2;
    float4 v0 = p[0], v1 = p[1];
    __nv_bfloat162 b0 = __floats2bfloat162_rn(v0.x, v0.y);
    __nv_bfloat162 b1 = __floats2bfloat162_rn(v0.z, v0.w);
    __nv_bfloat162 b2 = __floats2bfloat162_rn(v1.x, v1.y);
    __nv_bfloat162 b3 = __floats2bfloat162_rn(v1.z, v1.w);
    uint4 o;
    o.x = *reinterpret_cast<unsigned*>(&b0);
    o.y = *reinterpret_cast<unsigned*>(&b1);
    o.z = *reinterpret_cast<unsigned*>(&b2);
    o.w = *reinterpret_cast<unsigned*>(&b3);
    *((uint4*)out + i) = o;
}

__global__ __launch_bounds__(256) void cvt_x_kernel(const float* __restrict__ in) {
    int i = blockIdx.x * 256 + threadIdx.x;
    if (i < (M_ * D_) / 8) cvt8(in, g_xb, i);
}
__global__ __launch_bounds__(256) void cvt_w_kernel(const float* __restrict__ in) {
    int i = blockIdx.x * 256 + threadIdx.x;
    if (i < (D_ * C_) / 8) cvt8(in, g_Wb, i);
}

// ---------------- 1) bf16 tensor-core GEMM ----------------
// C(128x128 per block) = x_bf16 (M,D) @ W_bf16 (D,C) + bias ; fp32 accum
#define PADA 8
#define PADB 8
__global__ __launch_bounds__(256) void gemm_bf16_kernel(const float* __restrict__ bias)
{
    __shared__ __nv_bfloat16 As[2][128][16 + PADA];
    __shared__ __nv_bfloat16 Bs[2][16][128 + PADB];

    const int tid = threadIdx.x;
    const int wid = tid >> 5, lane = tid & 31;
    const int bm = blockIdx.y, bn = blockIdx.x;
    const int wm = wid & 1, wn = wid >> 1;   // warps: 2 (m) x 4 (n), each 64x32

    // gmem staging coords (one 16B load per thread per tile)
    const int arow = tid >> 1, acol = (tid & 1) * 8;
    const int brow = tid >> 4, bcol = (tid & 15) * 8;
    const __nv_bfloat16* gA = g_xb + (size_t)(bm * 128 + arow) * D_ + acol;
    const __nv_bfloat16* gB = g_Wb + (size_t)brow * C_ + bn * 128 + bcol;

    // ldmatrix lane addressing
    const int aRow = wm * 64 + (lane & 7) + ((lane >> 3) & 1) * 8;  // + mt*16
    const int aCol = ((lane >> 4) & 1) * 8;
    const int bRow = (lane & 7) + ((lane >> 3) & 1) * 8;
    const int bColBase = wn * 32 + ((lane >> 4) & 1) * 8;           // + pair*16

    const uint32_t aBase = (uint32_t)__cvta_generic_to_shared(&As[0][0][0]);
    const uint32_t bBase = (uint32_t)__cvta_generic_to_shared(&Bs[0][0][0]);
    const uint32_t AbufSz = sizeof(As[0]);
    const uint32_t BbufSz = sizeof(Bs[0]);

    float acc[4][4][4];
#pragma unroll
    for (int mt = 0; mt < 4; mt++)
#pragma unroll
        for (int nt = 0; nt < 4; nt++)
#pragma unroll
            for (int j = 0; j < 4; j++) acc[mt][nt][j] = 0.0f;

    // preload k-tile 0
    *(uint4*)&As[0][arow][acol] = *(const uint4*)gA;
    *(uint4*)&Bs[0][brow][bcol] = *(const uint4*)gB;
    __syncthreads();

    const int NKT = D_ / 16;   // 32
    for (int kt = 0; kt < NKT; kt++) {
        const int buf = kt & 1;
        uint4 la, lb;
        if (kt + 1 < NKT) {
            la = *(const uint4*)(gA + (kt + 1) * 16);
            lb = *(const uint4*)(gB + (size_t)(kt + 1) * 16 * C_);
        }

        uint32_t a[4][4], b[2][4];
#pragma unroll
        for (int mt = 0; mt < 4; mt++) {
            uint32_t addr = aBase + buf * AbufSz +
                            ((aRow + mt * 16) * (16 + PADA) + aCol) * 2;
            asm volatile("ldmatrix.sync.aligned.m8n8.x4.shared.b16 {%0,%1,%2,%3}, [%4];"
                : "=r"(a[mt][0]), "=r"(a[mt][1]), "=r"(a[mt][2]), "=r"(a[mt][3])
                : "r"(addr));
        }
#pragma unroll
        for (int pr = 0; pr < 2; pr++) {
            uint32_t addr = bBase + buf * BbufSz +
                            (bRow * (128 + PADB) + bColBase + pr * 16) * 2;
            asm volatile("ldmatrix.sync.aligned.m8n8.x4.trans.shared.b16 {%0,%1,%2,%3}, [%4];"
                : "=r"(b[pr][0]), "=r"(b[pr][1]), "=r"(b[pr][2]), "=r"(b[pr][3])
                : "r"(addr));
        }

#pragma unroll
        for (int mt = 0; mt < 4; mt++)
#pragma unroll
            for (int nt = 0; nt < 4; nt++) {
                uint32_t b0 = b[nt >> 1][(nt & 1) * 2 + 0];
                uint32_t b1 = b[nt >> 1][(nt & 1) * 2 + 1];
                asm volatile(
                    "mma.sync.aligned.m16n8k16.row.col.f32.bf16.bf16.f32 "
                    "{%0,%1,%2,%3}, {%4,%5,%6,%7}, {%8,%9}, {%0,%1,%2,%3};"
                    : "+f"(acc[mt][nt][0]), "+f"(acc[mt][nt][1]),
                      "+f"(acc[mt][nt][2]), "+f"(acc[mt][nt][3])
                    : "r"(a[mt][0]), "r"(a[mt][1]), "r"(a[mt][2]), "r"(a[mt][3]),
                      "r"(b0), "r"(b1));
            }

        if (kt + 1 < NKT) {
            int nb = buf ^ 1;
            *(uint4*)&As[nb][arow][acol] = la;
            *(uint4*)&Bs[nb][brow][bcol] = lb;
        }
        __syncthreads();
    }

    // epilogue: add bias, store fp32 logits
    const int tig = lane & 3, grp = lane >> 2;
#pragma unroll
    for (int mt = 0; mt < 4; mt++) {
        int row0 = bm * 128 + wm * 64 + mt * 16 + grp;
#pragma unroll
        for (int nt = 0; nt < 4; nt++) {
            int col = bn * 128 + wn * 32 + nt * 8 + 2 * tig;
            float b0v = bias[col], b1v = bias[col + 1];
            float2 v0 = make_float2(acc[mt][nt][0] + b0v, acc[mt][nt][1] + b1v);
            float2 v1 = make_float2(acc[mt][nt][2] + b0v, acc[mt][nt][3] + b1v);
            *(float2*)&g_logits[(size_t)row0 * C_ + col] = v0;
            *(float2*)&g_logits[(size_t)(row0 + 8) * C_ + col] = v1;
        }
    }
}

// ---------------- 2) per-row logsumexp ----------------
__global__ __launch_bounds__(256) void lse_kernel()
{
    int r = blockIdx.x;
    const float4* row = (const float4*)(g_logits + (size_t)r * C_);
    int tid = threadIdx.x;

    float4 v[4];
#pragma unroll
    for (int i = 0; i < 4; i++) v[i] = row[tid + 256 * i];

    float mx = -1e30f;
#pragma unroll
    for (int i = 0; i < 4; i++)
        mx = fmaxf(mx, fmaxf(fmaxf(v[i].x, v[i].y), fmaxf(v[i].z, v[i].w)));

    __shared__ float red[256];
    red[tid] = mx;
    __syncthreads();
    for (int s = 128; s > 0; s >>= 1) {
        if (tid < s) red[tid] = fmaxf(red[tid], red[tid + s]);
        __syncthreads();
    }
    mx = red[0];
    __syncthreads();

    float sum = 0.0f;
#pragma unroll
    for (int i = 0; i < 4; i++)
        sum += __expf(v[i].x - mx) + __expf(v[i].y - mx) +
               __expf(v[i].z - mx) + __expf(v[i].w - mx);
    red[tid] = sum;
    __syncthreads();
    for (int s = 128; s > 0; s >>= 1) {
        if (tid < s) red[tid] += red[tid + s];
        __syncthreads();
    }
    if (tid == 0) g_lse[r] = mx + __logf(red[0]);
}

// ---------------- 3) gather lp ----------------
#define GT 8
__global__ __launch_bounds__(128) void gather_kernel(
    const int* __restrict__ tgt1, const int* __restrict__ tgt2,
    const int* __restrict__ act_lens,
    const int* __restrict__ tl1, const int* __restrict__ tl2)
{
    int chain = blockIdx.y;
    int s = chain >> 4, b = chain & 15;
    const int* tgt = (s ? tgt2 : tgt1) + b * U_;
    int tlen = (s ? tl2 : tl1)[b];
    int alen = act_lens[b];

    int t0 = blockIdx.x * GT;
    if (t0 >= alen) return;
    int te = min(t0 + GT, alen);

    int tid = threadIdx.x;
    int c[4];
    int nu = 0;
    for (int u = tid; u < tlen; u += 128) c[nu++] = tgt[u];

    float* lpc = g_lp + (size_t)chain * T_ * U_;
    for (int t = t0; t < te; t++) {
        const float* lrow = g_logits + (size_t)(b * T_ + t) * C_;
        float lse = g_lse[b * T_ + t];
        float* lprow = lpc + (size_t)t * U_;
        int u = tid;
        for (int i = 0; i < nu; i++, u += 128)
            lprow[u] = __ldg(lrow + c[i]) - lse;
    }
}

// ---------------- 4) alpha recursion: ONE WARP per chain ----------------
#define E_ 13   // 13*32 = 416 >= U_
__device__ __forceinline__ void stepf(float* a, const float* c, int lane)
{
    float up = __shfl_up_sync(0xffffffffu, a[E_ - 1], 1);
    if (lane == 0) up = NEGF;
    float prev = up;
#pragma unroll
    for (int i = 0; i < E_; i++) {
        float old = a[i];
        a[i] = laef(old, prev) + c[i];
        prev = old;
    }
}

__global__ __launch_bounds__(32) void alpha_kernel(
    const int* __restrict__ act_lens,
    const int* __restrict__ tl1, const int* __restrict__ tl2)
{
    int chain = blockIdx.x;
    int s = chain >> 4, b = chain & 15;
    int tlen = (s ? tl2 : tl1)[b];
    int alen = act_lens[b];          // guaranteed >= T_/2 = 1000
    int lane = threadIdx.x;
    const float* lp = g_lp + (size_t)chain * T_ * U_;

    __shared__ float sb[2][416];
    float a[E_], pfA[E_], pfB[E_];
    int u0 = lane * E_;

    // init from row 0
#pragma unroll
    for (int i = 0; i < E_; i++) {
        int u = u0 + i;
        float v = (u < U_) ? lp[u] : NEGF;
        a[i] = v + ((u == 0) ? 0.0f : NEGF);
    }

    // prologue: rows 1,2 -> smem; rows 3,4 -> prefetch regs
#pragma unroll
    for (int j = 0; j < E_; j++) {
        int idx = lane + 32 * j;
        bool ok = idx < U_;
        sb[1][idx] = ok ? lp[(size_t)1 * U_ + idx] : NEGF;
        sb[0][idx] = ok ? lp[(size_t)2 * U_ + idx] : NEGF;
        pfA[j] = (ok && 3 < alen) ? lp[(size_t)3 * U_ + idx] : NEGF;
        pfB[j] = (ok && 4 < alen) ? lp[(size_t)4 * U_ + idx] : NEGF;
    }
    __syncwarp();

    float c[E_];
    int t = 1;
    for (; t + 1 < alen; t += 2) {
        // phase 1: row t (in sb[1])
#pragma unroll
        for (int i = 0; i < E_; i++) c[i] = sb[1][u0 + i];
        stepf(a, c, lane);
        __syncwarp();
#pragma unroll
        for (int j = 0; j < E_; j++) {
            int idx = lane + 32 * j;
            sb[1][idx] = pfA[j];
            pfA[j] = (t + 4 < alen && idx < U_) ? lp[(size_t)(t + 4) * U_ + idx] : NEGF;
        }
        __syncwarp();
        // phase 2: row t+1 (in sb[0])
#pragma unroll
        for (int i = 0; i < E_; i++) c[i] = sb[0][u0 + i];
        stepf(a, c, lane);
        __syncwarp();
#pragma unroll
        for (int j = 0; j < E_; j++) {
            int idx = lane + 32 * j;
            sb[0][idx] = pfB[j];
            pfB[j] = (t + 5 < alen && idx < U_) ? lp[(size_t)(t + 5) * U_ + idx] : NEGF;
        }
        __syncwarp();
    }
    if (t < alen) {   // one remaining step, row t lives in sb[1]
#pragma unroll
        for (int i = 0; i < E_; i++) c[i] = sb[1][u0 + i];
        stepf(a, c, lane);
    }

    int ustar = tlen - 1;
    int own = ustar / E_, slot = ustar % E_;
    float v = 0.0f;
#pragma unroll
    for (int i = 0; i < E_; i++)
        if (i == slot) v = a[i];
    v = __shfl_sync(0xffffffffu, v, own);
    if (lane == 0) g_loss[chain] = -v;
}

// ---------------- 5) final reduction ----------------
__global__ void loss_kernel(float* out)
{
    if (threadIdx.x == 0) {
        float l1 = 0.0f, l2 = 0.0f;
        for (int i = 0; i < 16; i++) { l1 += g_loss[i]; l2 += g_loss[16 + i]; }
        l1 *= (1.0f / 16.0f);
        l2 *= (1.0f / 16.0f);
        out[0] = l1 - 0.5f * l2;
        out[1] = l1;
        out[2] = l2;
    }
}

// ---------------- launch ----------------
extern "C" void kernel_launch(void* const* d_in, const int* in_sizes, int n_in,
                              void* d_out, int out_size)
{
    const float* x    = (const float*)d_in[0];
    const float* W    = (const float*)d_in[1];
    const float* bias = (const float*)d_in[2];
    const int* tgt1   = (const int*)d_in[3];
    const int* tgt2   = (const int*)d_in[4];
    const int* alen   = (const int*)d_in[5];
    const int* tl1    = (const int*)d_in[6];
    const int* tl2    = (const int*)d_in[7];
    float* out = (float*)d_out;

    cvt_x_kernel<<<(M_ * D_ / 8 + 255) / 256, 256>>>(x);
    cvt_w_kernel<<<(D_ * C_ / 8 + 255) / 256, 256>>>(W);

    dim3 ggrid(C_ / 128, M_ / 128);          // (32, 250)
    gemm_bf16_kernel<<<ggrid, 256>>>(bias);

    lse_kernel<<<M_, 256>>>();

    dim3 grid_g((T_ + GT - 1) / GT, 2 * B_); // (250, 32)
    gather_kernel<<<grid_g, 128>>>(tgt1, tgt2, alen, tl1, tl2);

    alpha_kernel<<<2 * B_, 32>>>(alen, tl1, tl2);

    loss_kernel<<<1, 32>>>(out);
}